// round 8
// baseline (speedup 1.0000x reference)
#include <cuda_runtime.h>

#define NCO     513
#define NPAIRS  256
#define STEP    512
#define PI_F    3.14159265358979323846f

// ---- persistent device scratch ----
__device__ float  g_u[NPAIRS * NCO];
__device__ float  g_v[NPAIRS * NCO];
__device__ float  g_d[NPAIRS * NCO];     // decay magnitude d
__device__ float  g_e[NPAIRS * NCO];     // signed: (k odd ? -d : d)
__device__ float  g_d2[NPAIRS * NCO];    // d*d
__device__ float4 g_C[NPAIRS * 512];     // build coeffs (C1r,C1i,C2r,C2i)
__device__ float2 g_win2[512];           // Hann pairs (win[2n], win[2n+1])

// ---------------------------------------------------------------------------
__global__ void init_win_kernel() {
    int i = threadIdx.x;  // 0..511
    float w0 = 0.5f - 0.5f * cospif((2 * i    ) * (1.0f / 512.0f));
    float w1 = 0.5f - 0.5f * cospif((2 * i + 1) * (1.0f / 512.0f));
    g_win2[i] = make_float2(w0, w1);
}

__global__ void init_base_kernel(const float* __restrict__ amp,
                                 const float* __restrict__ phase,
                                 const float* __restrict__ decay) {
    int idx = blockIdx.x * 256 + threadIdx.x;
    if (idx >= 64 * NCO * 4) return;
    int e  = idx & 3;
    int rk = idx >> 2;
    int k  = rk % NCO;
    int r  = rk / NCO;

    float a  = amp[idx];
    float ph = phase[idx];
    float dc = decay[idx];

    float d  = 0.5f + 0.45f / (1.0f + expf(-dc));
    float sp = tanhf(ph) * PI_F;
    float m0 = fabsf(a) + 1e-12f;
    float sn, cs;
    sincosf(sp, &sn, &cs);

    const float sc = 1.0f / 1024.0f;
    int o = (r * 4 + e) * NCO + k;
    g_u[o]  = m0 * cs * sc;
    g_v[o]  = m0 * sn * sc;
    g_d[o]  = d;
    g_e[o]  = (k & 1) ? -d : d;
    g_d2[o] = d * d;
}

__global__ void init_pack_kernel() {
    int idx = blockIdx.x * 256 + threadIdx.x;
    if (idx >= NPAIRS * 512) return;
    int k    = idx & 511;
    int pair = idx >> 9;
    const float* U = g_u + pair * NCO;
    const float* V = g_v + pair * NCO;
    float4 c;
    if (k == 0) {
        c = make_float4(U[0], U[0], U[512], -U[512]);
    } else {
        int q = 512 - k;
        float ty, tx;
        sincospif(k * (1.0f / 512.0f), &ty, &tx);
        float suk = U[k], svk = V[k], suq = U[q], svq = V[q];
        c.x =  suk * (1.0f - ty) - tx * svk;
        c.y =  svk * (1.0f - ty) + tx * suk;
        c.z =  suq * (1.0f + ty) - tx * svq;
        c.w = -svq * (1.0f + ty) - tx * suq;
    }
    g_C[idx] = c;
}

// ---------------------------------------------------------------------------
// packed f32x2 primitives (two frames per 64-bit register)
// ---------------------------------------------------------------------------
typedef unsigned long long pk;

__device__ __forceinline__ pk PK(float lo, float hi) {
    pk r; asm("mov.b64 %0, {%1, %2};" : "=l"(r) : "f"(lo), "f"(hi)); return r;
}
__device__ __forceinline__ pk PDUP(float v) { return PK(v, v); }
__device__ __forceinline__ void UNPK(pk a, float& lo, float& hi) {
    asm("mov.b64 {%0, %1}, %2;" : "=f"(lo), "=f"(hi) : "l"(a));
}
__device__ __forceinline__ pk PADD(pk a, pk b) {
    pk r; asm("add.rn.f32x2 %0, %1, %2;" : "=l"(r) : "l"(a), "l"(b)); return r;
}
__device__ __forceinline__ pk PMUL(pk a, pk b) {
    pk r; asm("mul.rn.f32x2 %0, %1, %2;" : "=l"(r) : "l"(a), "l"(b)); return r;
}
__device__ __forceinline__ pk PFMA(pk a, pk b, pk c) {
    pk r; asm("fma.rn.f32x2 %0, %1, %2, %3;" : "=l"(r) : "l"(a), "l"(b), "l"(c)); return r;
}

struct cpk { pk re, im; };

#define RHF 0.70710678118654752440f

// inverse DFT-8 on packed (2-frame) complex registers
__device__ __forceinline__ void fft8p(cpk* a, pk M1, pk RH2, pk NRH2) {
    // PSUB(x,y) = PFMA(y, M1, x)
    cpk t0, t1, t2, t3, s0, s1, s2, s3, E0, E1, E2, E3, O0, O1, O2, O3;
    t0.re = PADD(a[0].re, a[4].re);  t0.im = PADD(a[0].im, a[4].im);
    t1.re = PFMA(a[4].re, M1, a[0].re);  t1.im = PFMA(a[4].im, M1, a[0].im);
    t2.re = PADD(a[2].re, a[6].re);  t2.im = PADD(a[2].im, a[6].im);
    t3.re = PFMA(a[6].re, M1, a[2].re);  t3.im = PFMA(a[6].im, M1, a[2].im);
    E0.re = PADD(t0.re, t2.re);  E0.im = PADD(t0.im, t2.im);
    E2.re = PFMA(t2.re, M1, t0.re);  E2.im = PFMA(t2.im, M1, t0.im);
    E1.re = PFMA(t3.im, M1, t1.re);  E1.im = PADD(t1.im, t3.re);
    E3.re = PADD(t1.re, t3.im);      E3.im = PFMA(t3.re, M1, t1.im);
    s0.re = PADD(a[1].re, a[5].re);  s0.im = PADD(a[1].im, a[5].im);
    s1.re = PFMA(a[5].re, M1, a[1].re);  s1.im = PFMA(a[5].im, M1, a[1].im);
    s2.re = PADD(a[3].re, a[7].re);  s2.im = PADD(a[3].im, a[7].im);
    s3.re = PFMA(a[7].re, M1, a[3].re);  s3.im = PFMA(a[7].im, M1, a[3].im);
    O0.re = PADD(s0.re, s2.re);  O0.im = PADD(s0.im, s2.im);
    O2.re = PFMA(s2.re, M1, s0.re);  O2.im = PFMA(s2.im, M1, s0.im);
    O1.re = PFMA(s3.im, M1, s1.re);  O1.im = PADD(s1.im, s3.re);
    O3.re = PADD(s1.re, s3.im);      O3.im = PFMA(s3.re, M1, s1.im);

    a[0].re = PADD(E0.re, O0.re);  a[0].im = PADD(E0.im, O0.im);
    a[4].re = PFMA(O0.re, M1, E0.re);  a[4].im = PFMA(O0.im, M1, E0.im);
    // W2 = i*O2
    a[2].re = PFMA(O2.im, M1, E2.re);  a[2].im = PADD(E2.im, O2.re);
    a[6].re = PADD(E2.re, O2.im);      a[6].im = PFMA(O2.re, M1, E2.im);
    // W1 = RH*(O1.re-O1.im, O1.re+O1.im)
    pk m1 = PFMA(O1.im, M1, O1.re);
    pk p1 = PADD(O1.re, O1.im);
    a[1].re = PFMA(m1, RH2,  E1.re);  a[5].re = PFMA(m1, NRH2, E1.re);
    a[1].im = PFMA(p1, RH2,  E1.im);  a[5].im = PFMA(p1, NRH2, E1.im);
    // W3 = (-RH*(O3.re+O3.im), RH*(O3.re-O3.im))
    pk p3 = PADD(O3.re, O3.im);
    pk m3 = PFMA(O3.im, M1, O3.re);
    a[3].re = PFMA(p3, NRH2, E3.re);  a[7].re = PFMA(p3, RH2,  E3.re);
    a[3].im = PFMA(m3, RH2,  E3.im);  a[7].im = PFMA(m3, NRH2, E3.im);
}

__device__ __forceinline__ void cmulp(cpk& a, pk cc2, pk ss2, pk M1) {
    pk nre = PFMA(PMUL(a.im, ss2), M1, PMUL(a.re, cc2));
    a.im   = PFMA(a.re, ss2, PMUL(a.im, cc2));
    a.re   = nre;
}

__device__ __forceinline__ void gbar(int g) {
    asm volatile("bar.sync %0, %1;" :: "r"(g + 1), "r"(64) : "memory");
}

// ---------------------------------------------------------------------------
// One block = (pair, 32-hop chunk); 4 groups x 64 threads.
// Group g: frames [fstart .. fstart+7], two frames per iteration packed in
// f32x2 lanes. Overlap-add carry stays in registers (cross-lane intra-pair).
// ---------------------------------------------------------------------------
__global__ __launch_bounds__(256, 2) void synth_kernel(float* __restrict__ out) {
    __shared__ ulonglong2 exch[4][512];      // packed (re2, im2) exchange
    __shared__ float2 ccc[7][64], sss[7][64];// stage-1 twiddles, dup'd
    __shared__ float4 tw2d[7][8];            // stage-2 twiddles (c,c,s,s)
    __shared__ float2 winp[512];             // Hann pairs
    __shared__ float  sd2[NCO];              // d^2 per bin

    const int tid   = threadIdx.x;
    const int g     = tid >> 6;
    const int t     = tid & 63;
    const int pair  = blockIdx.x;
    const int chunk = blockIdx.y;
    const int fstart = chunk * 32 + g * 8;
    const int f0     = fstart ? (fstart - 1) : 0;
    const int NIT    = fstart ? 5 : 4;

    for (int i = tid; i < NCO; i += 256) sd2[i] = g_d2[pair * NCO + i];
    for (int i = tid; i < 512; i += 256) winp[i] = g_win2[i];
    for (int i = tid; i < 448; i += 256) {
        int j = i >> 6, tt = i & 63;
        float s, c;
        sincospif((float)((j + 1) * tt) * (1.0f / 256.0f), &s, &c);
        ccc[j][tt] = make_float2(c, c);
        sss[j][tt] = make_float2(s, s);
    }
    if (tid < 56) {
        int j = tid >> 3, pp = tid & 7;
        float s, c;
        sincospif((float)((j + 1) * pp) * (1.0f / 32.0f), &s, &c);
        tw2d[j][pp] = make_float4(c, c, s, s);
    }
    __syncthreads();

    const pk M1   = PDUP(-1.0f);
    const pk RH2  = PDUP(RHF);
    const pk NRH2 = PDUP(-RHF);

    // ---- per-thread persistent state ----
    float4 C[8];
    pk wk2[8], wq2[8];
    {
        const float f0f = (float)f0;
        #pragma unroll
        for (int r = 0; r < 8; ++r) {
            int k = t + 64 * r;
            int q = 512 - k;
            C[r] = g_C[pair * 512 + k];
            float dk = g_d[pair * NCO + k];
            float dq = g_d[pair * NCO + q];
            float ek = g_e[pair * NCO + k];
            float eq = g_e[pair * NCO + q];
            float wA  = exp2f(f0f * log2f(dk));
            float wqA = exp2f(f0f * log2f(dq));
            if ((f0 & 1) && (k & 1)) { wA = -wA; wqA = -wqA; }  // (-1)^{f0*k}
            wk2[r] = PK(wA,  wA  * ek);   // lanes: frame f0, f0+1
            wq2[r] = PK(wqA, wqA * eq);
        }
    }
    float2 carry[4];
    #pragma unroll
    for (int j = 0; j < 4; ++j) carry[j] = make_float2(0.0f, 0.0f);

    ulonglong2* buf = exch[g];
    float* outp = out + (size_t)pair * 65536;
    const int t7 = t & 7, th = t >> 3;

    for (int it = 0; it < NIT; ++it) {
        const int fA = f0 + 2 * it;
        const int fB = fA + 1;
        cpk a[8];

        // ---- build spectrum (both frames at once) ----
        #pragma unroll
        for (int r = 0; r < 8; ++r) {
            a[r].re = PFMA(wq2[r], PDUP(C[r].z), PMUL(wk2[r], PDUP(C[r].x)));
            a[r].im = PFMA(wq2[r], PDUP(C[r].w), PMUL(wk2[r], PDUP(C[r].y)));
        }

        // ---- stage 1 (s=1) ----
        fft8p(a, M1, RH2, NRH2);
        #pragma unroll
        for (int j = 1; j < 8; ++j) {
            pk cc2 = *(const pk*)&ccc[j - 1][t];
            pk ss2 = *(const pk*)&sss[j - 1][t];
            cmulp(a[j], cc2, ss2, M1);
        }
        #pragma unroll
        for (int j = 0; j < 8; ++j) {        // write x = 8t+j, px = x ^ (t&7)
            int px = (8 * t + j) ^ t7;
            ulonglong2 v; v.x = a[j].re; v.y = a[j].im;
            buf[px] = v;
        }
        gbar(g);
        #pragma unroll
        for (int r = 0; r < 8; ++r) {        // read x = t+64r, px = x ^ (t>>3)
            int px = (t + 64 * r) ^ th;
            ulonglong2 v = buf[px];
            a[r].re = v.x; a[r].im = v.y;
        }
        gbar(g);                             // WAR before stage-2 writes

        // ---- stage 2 (s=8) ----
        fft8p(a, M1, RH2, NRH2);
        #pragma unroll
        for (int j = 1; j < 8; ++j) {
            pk cc2 = *(const pk*)&tw2d[j - 1][th].x;
            pk ss2 = *(const pk*)&tw2d[j - 1][th].z;
            cmulp(a[j], cc2, ss2, M1);
        }
        #pragma unroll
        for (int j = 0; j < 8; ++j) {        // write x = (t&7)+64(t>>3)+8j, px = x ^ j
            int px = (t7 + 64 * th + 8 * j) ^ j;
            ulonglong2 v; v.x = a[j].re; v.y = a[j].im;
            buf[px] = v;
        }
        gbar(g);
        #pragma unroll
        for (int r = 0; r < 8; ++r) {        // read x = t+64r, px = x ^ (t>>3)
            int px = (t + 64 * r) ^ th;
            ulonglong2 v = buf[px];
            a[r].re = v.x; a[r].im = v.y;
        }
        gbar(g);                             // WAR before next iteration's writes

        // ---- stage 3 (s=64): z[t+64j] packed in registers ----
        fft8p(a, M1, RH2, NRH2);

        // ---- window + overlap-add epilogue ----
        const bool sA = (fA >= fstart);
        const bool sB = (fB <= fstart + 7);
        #pragma unroll
        for (int j = 0; j < 4; ++j) {
            int n1 = t + 64 * j;
            int n2 = n1 + 256;
            float reA, reB, imA, imB, r2A, r2B, i2A, i2B;
            UNPK(a[j].re, reA, reB);     UNPK(a[j].im, imA, imB);
            UNPK(a[j + 4].re, r2A, r2B); UNPK(a[j + 4].im, i2A, i2B);
            float2 w1 = winp[n1];
            float2 w2 = winp[n2];
            if (sA) {
                float2 o;
                o.x = reA * w1.x + carry[j].x;
                o.y = imA * w1.y + carry[j].y;
                *(float2*)(outp + (size_t)fA * STEP + 2 * n1) = o;
            }
            if (sB) {
                float2 o;
                o.x = reB * w1.x + r2A * w2.x;
                o.y = imB * w1.y + i2A * w2.y;
                *(float2*)(outp + (size_t)fB * STEP + 2 * n1) = o;
            }
            carry[j] = make_float2(r2B * w2.x, i2B * w2.y);
        }

        // ---- advance decay by d^2 (both lanes; parity preserved) ----
        #pragma unroll
        for (int r = 0; r < 8; ++r) {
            int k = t + 64 * r;
            wk2[r] = PMUL(wk2[r], PDUP(sd2[k]));
            wq2[r] = PMUL(wq2[r], PDUP(sd2[512 - k]));
        }
    }
}

// ---------------------------------------------------------------------------
extern "C" void kernel_launch(void* const* d_in, const int* in_sizes, int n_in,
                              void* d_out, int out_size) {
    const float* amp   = (const float*)d_in[0];
    const float* phase = (const float*)d_in[1];
    const float* decay = (const float*)d_in[2];
    float* out = (float*)d_out;

    init_win_kernel<<<1, 512>>>();
    int total = 64 * NCO * 4;
    init_base_kernel<<<(total + 255) / 256, 256>>>(amp, phase, decay);
    init_pack_kernel<<<(NPAIRS * 512 + 255) / 256, 256>>>();

    dim3 grid(NPAIRS, 4);
    synth_kernel<<<grid, 256>>>(out);
}

// round 10
// speedup vs baseline: 1.1940x; 1.1940x over previous
#include <cuda_runtime.h>

#define NCO     513
#define NPAIRS  256
#define STEP    512
#define PI_F    3.14159265358979323846f

// ---- persistent device scratch ----
__device__ float  g_u[NPAIRS * NCO];
__device__ float  g_v[NPAIRS * NCO];
__device__ float  g_d[NPAIRS * NCO];     // decay magnitude d
__device__ float  g_e[NPAIRS * NCO];     // signed: (k odd ? -d : d)
__device__ float  g_d2[NPAIRS * NCO];    // d*d
__device__ float4 g_C[NPAIRS * 512];     // build coeffs (C1r,C1i,C2r,C2i)

// ---------------------------------------------------------------------------
__global__ void init_base_kernel(const float* __restrict__ amp,
                                 const float* __restrict__ phase,
                                 const float* __restrict__ decay) {
    int idx = blockIdx.x * 256 + threadIdx.x;
    if (idx >= 64 * NCO * 4) return;
    int e  = idx & 3;
    int rk = idx >> 2;
    int k  = rk % NCO;
    int r  = rk / NCO;

    float a  = amp[idx];
    float ph = phase[idx];
    float dc = decay[idx];

    float d  = 0.5f + 0.45f / (1.0f + expf(-dc));
    float sp = tanhf(ph) * PI_F;
    float m0 = fabsf(a) + 1e-12f;
    float sn, cs;
    sincosf(sp, &sn, &cs);

    const float sc = 1.0f / 1024.0f;
    int o = (r * 4 + e) * NCO + k;
    g_u[o]  = m0 * cs * sc;
    g_v[o]  = m0 * sn * sc;
    g_d[o]  = d;
    g_e[o]  = (k & 1) ? -d : d;
    g_d2[o] = d * d;
}

__global__ void init_pack_kernel() {
    int idx = blockIdx.x * 256 + threadIdx.x;
    if (idx >= NPAIRS * 512) return;
    int k    = idx & 511;
    int pair = idx >> 9;
    const float* U = g_u + pair * NCO;
    const float* V = g_v + pair * NCO;
    float4 c;
    if (k == 0) {
        c = make_float4(U[0], U[0], U[512], -U[512]);
    } else {
        int q = 512 - k;
        float ty, tx;
        sincospif(k * (1.0f / 512.0f), &ty, &tx);
        float suk = U[k], svk = V[k], suq = U[q], svq = V[q];
        c.x =  suk * (1.0f - ty) - tx * svk;
        c.y =  svk * (1.0f - ty) + tx * suk;
        c.z =  suq * (1.0f + ty) - tx * svq;
        c.w = -svq * (1.0f + ty) - tx * suq;
    }
    g_C[idx] = c;
}

// ---------------------------------------------------------------------------
// packed f32x2 primitives (two frames per 64-bit register)
// ---------------------------------------------------------------------------
typedef unsigned long long pk;

__device__ __forceinline__ pk PK(float lo, float hi) {
    pk r; asm("mov.b64 %0, {%1, %2};" : "=l"(r) : "f"(lo), "f"(hi)); return r;
}
__device__ __forceinline__ pk PDUP(float v) { return PK(v, v); }
__device__ __forceinline__ void UNPK(pk a, float& lo, float& hi) {
    asm("mov.b64 {%0, %1}, %2;" : "=f"(lo), "=f"(hi) : "l"(a));
}
__device__ __forceinline__ pk PADD(pk a, pk b) {
    pk r; asm("add.rn.f32x2 %0, %1, %2;" : "=l"(r) : "l"(a), "l"(b)); return r;
}
__device__ __forceinline__ pk PMUL(pk a, pk b) {
    pk r; asm("mul.rn.f32x2 %0, %1, %2;" : "=l"(r) : "l"(a), "l"(b)); return r;
}
__device__ __forceinline__ pk PFMA(pk a, pk b, pk c) {
    pk r; asm("fma.rn.f32x2 %0, %1, %2, %3;" : "=l"(r) : "l"(a), "l"(b), "l"(c)); return r;
}

struct cpk { pk re, im; };

#define RHF 0.70710678118654752440f

// inverse DFT-8 on packed (2-frame) complex registers
__device__ __forceinline__ void fft8p(cpk* a, pk M1, pk RH2, pk NRH2) {
    cpk t0, t1, t2, t3, s0, s1, s2, s3, E0, E1, E2, E3, O0, O1, O2, O3;
    t0.re = PADD(a[0].re, a[4].re);  t0.im = PADD(a[0].im, a[4].im);
    t1.re = PFMA(a[4].re, M1, a[0].re);  t1.im = PFMA(a[4].im, M1, a[0].im);
    t2.re = PADD(a[2].re, a[6].re);  t2.im = PADD(a[2].im, a[6].im);
    t3.re = PFMA(a[6].re, M1, a[2].re);  t3.im = PFMA(a[6].im, M1, a[2].im);
    E0.re = PADD(t0.re, t2.re);  E0.im = PADD(t0.im, t2.im);
    E2.re = PFMA(t2.re, M1, t0.re);  E2.im = PFMA(t2.im, M1, t0.im);
    E1.re = PFMA(t3.im, M1, t1.re);  E1.im = PADD(t1.im, t3.re);
    E3.re = PADD(t1.re, t3.im);      E3.im = PFMA(t3.re, M1, t1.im);
    s0.re = PADD(a[1].re, a[5].re);  s0.im = PADD(a[1].im, a[5].im);
    s1.re = PFMA(a[5].re, M1, a[1].re);  s1.im = PFMA(a[5].im, M1, a[1].im);
    s2.re = PADD(a[3].re, a[7].re);  s2.im = PADD(a[3].im, a[7].im);
    s3.re = PFMA(a[7].re, M1, a[3].re);  s3.im = PFMA(a[7].im, M1, a[3].im);
    O0.re = PADD(s0.re, s2.re);  O0.im = PADD(s0.im, s2.im);
    O2.re = PFMA(s2.re, M1, s0.re);  O2.im = PFMA(s2.im, M1, s0.im);
    O1.re = PFMA(s3.im, M1, s1.re);  O1.im = PADD(s1.im, s3.re);
    O3.re = PADD(s1.re, s3.im);      O3.im = PFMA(s3.re, M1, s1.im);

    a[0].re = PADD(E0.re, O0.re);  a[0].im = PADD(E0.im, O0.im);
    a[4].re = PFMA(O0.re, M1, E0.re);  a[4].im = PFMA(O0.im, M1, E0.im);
    a[2].re = PFMA(O2.im, M1, E2.re);  a[2].im = PADD(E2.im, O2.re);
    a[6].re = PADD(E2.re, O2.im);      a[6].im = PFMA(O2.re, M1, E2.im);
    pk m1 = PFMA(O1.im, M1, O1.re);
    pk p1 = PADD(O1.re, O1.im);
    a[1].re = PFMA(m1, RH2,  E1.re);  a[5].re = PFMA(m1, NRH2, E1.re);
    a[1].im = PFMA(p1, RH2,  E1.im);  a[5].im = PFMA(p1, NRH2, E1.im);
    pk p3 = PADD(O3.re, O3.im);
    pk m3 = PFMA(O3.im, M1, O3.re);
    a[3].re = PFMA(p3, NRH2, E3.re);  a[7].re = PFMA(p3, RH2,  E3.re);
    a[3].im = PFMA(m3, RH2,  E3.im);  a[7].im = PFMA(m3, NRH2, E3.im);
}

__device__ __forceinline__ void cmulp(cpk& a, pk cc2, pk ss2, pk M1) {
    pk nre = PFMA(PMUL(a.im, ss2), M1, PMUL(a.re, cc2));
    a.im   = PFMA(a.re, ss2, PMUL(a.im, cc2));
    a.re   = nre;
}

__device__ __forceinline__ void gbar(int g) {
    asm volatile("bar.sync %0, %1;" :: "r"(g + 1), "r"(64) : "memory");
}

// ---------------------------------------------------------------------------
// One block = (pair, 32-hop chunk); 4 groups x 64 threads.
// Two frames per iteration packed in f32x2 lanes; coeffs in smem; window in
// registers; decay recurrence in packed registers. ~46 KB smem, no spills.
// ---------------------------------------------------------------------------
__global__ __launch_bounds__(256, 2) void synth_kernel(float* __restrict__ out) {
    __shared__ ulonglong2 exch[4][512];      // packed (re2, im2) exchange
    __shared__ float2 tws1[7][64];           // stage-1 twiddles (c,s)
    __shared__ float2 tws2[7][8];            // stage-2 twiddles (c,s)
    __shared__ float  sd2[NCO];              // d^2 per bin
    __shared__ float4 sC[512];               // build coeffs

    const int tid   = threadIdx.x;
    const int g     = tid >> 6;
    const int t     = tid & 63;
    const int pair  = blockIdx.x;
    const int chunk = blockIdx.y;
    const int fstart = chunk * 32 + g * 8;
    const int f0     = fstart ? (fstart - 1) : 0;
    const int NIT    = fstart ? 5 : 4;

    for (int i = tid; i < NCO; i += 256) sd2[i] = g_d2[pair * NCO + i];
    for (int i = tid; i < 512; i += 256) sC[i]  = g_C[pair * 512 + i];
    for (int i = tid; i < 448; i += 256) {
        int j = i >> 6, tt = i & 63;
        float s, c;
        sincospif((float)((j + 1) * tt) * (1.0f / 256.0f), &s, &c);
        tws1[j][tt] = make_float2(c, s);
    }
    if (tid < 56) {
        int j = tid >> 3, pp = tid & 7;
        float s, c;
        sincospif((float)((j + 1) * pp) * (1.0f / 32.0f), &s, &c);
        tws2[j][pp] = make_float2(c, s);
    }
    __syncthreads();

    const pk M1   = PDUP(-1.0f);
    const pk RH2  = PDUP(RHF);
    const pk NRH2 = PDUP(-RHF);

    // ---- per-thread persistent state ----
    pk     wk2[8], wq2[8];
    float2 wA[8];                            // Hann pairs, n = t+64j
    {
        const float f0f = (float)f0;
        #pragma unroll
        for (int r = 0; r < 8; ++r) {
            int k = t + 64 * r;
            int q = 512 - k;
            float dk = g_d[pair * NCO + k];
            float dq = g_d[pair * NCO + q];
            float ek = g_e[pair * NCO + k];
            float eq = g_e[pair * NCO + q];
            float w  = exp2f(f0f * log2f(dk));
            float wq = exp2f(f0f * log2f(dq));
            if ((f0 & 1) && (k & 1)) { w = -w; wq = -wq; }   // (-1)^{f0*k}
            wk2[r] = PK(w,  w  * ek);        // lanes: frame f0, f0+1
            wq2[r] = PK(wq, wq * eq);
        }
        #pragma unroll
        for (int j = 0; j < 8; ++j) {
            int n = t + 64 * j;
            wA[j].x = 0.5f - 0.5f * cospif((float)n * (1.0f / 256.0f));
            wA[j].y = 0.5f - 0.5f * cospif((float)(2 * n + 1) * (1.0f / 512.0f));
        }
    }
    float2 carry[4];
    #pragma unroll
    for (int j = 0; j < 4; ++j) carry[j] = make_float2(0.0f, 0.0f);

    ulonglong2* buf = exch[g];
    float* outp = out + (size_t)pair * 65536;
    const int t7 = t & 7, th = t >> 3;

    for (int it = 0; it < NIT; ++it) {
        const int fA = f0 + 2 * it;
        const int fB = fA + 1;
        cpk a[8];

        // ---- build spectrum (both frames at once; coeffs from smem) ----
        #pragma unroll
        for (int r = 0; r < 8; ++r) {
            float4 c = sC[t + 64 * r];
            a[r].re = PFMA(wq2[r], PDUP(c.z), PMUL(wk2[r], PDUP(c.x)));
            a[r].im = PFMA(wq2[r], PDUP(c.w), PMUL(wk2[r], PDUP(c.y)));
        }

        // ---- stage 1 (s=1) ----
        fft8p(a, M1, RH2, NRH2);
        #pragma unroll
        for (int j = 1; j < 8; ++j) {
            float2 cs = tws1[j - 1][t];
            cmulp(a[j], PDUP(cs.x), PDUP(cs.y), M1);
        }
        #pragma unroll
        for (int j = 0; j < 8; ++j) {        // write x = 8t+j, px = x ^ (t&7)
            int px = (8 * t + j) ^ t7;
            ulonglong2 v; v.x = a[j].re; v.y = a[j].im;
            buf[px] = v;
        }
        gbar(g);
        #pragma unroll
        for (int r = 0; r < 8; ++r) {        // read x = t+64r, px = x ^ (t>>3)
            int px = (t + 64 * r) ^ th;
            ulonglong2 v = buf[px];
            a[r].re = v.x; a[r].im = v.y;
        }
        gbar(g);                             // WAR before stage-2 writes

        // ---- stage 2 (s=8) ----
        fft8p(a, M1, RH2, NRH2);
        #pragma unroll
        for (int j = 1; j < 8; ++j) {
            float2 cs = tws2[j - 1][th];
            cmulp(a[j], PDUP(cs.x), PDUP(cs.y), M1);
        }
        #pragma unroll
        for (int j = 0; j < 8; ++j) {        // write x = (t&7)+64(t>>3)+8j, px = x ^ j
            int px = (t7 + 64 * th + 8 * j) ^ j;
            ulonglong2 v; v.x = a[j].re; v.y = a[j].im;
            buf[px] = v;
        }
        gbar(g);
        #pragma unroll
        for (int r = 0; r < 8; ++r) {        // read x = t+64r, px = x ^ (t>>3)
            int px = (t + 64 * r) ^ th;
            ulonglong2 v = buf[px];
            a[r].re = v.x; a[r].im = v.y;
        }
        gbar(g);                             // WAR before next iteration's writes

        // ---- stage 3 (s=64): z[t+64j] packed in registers ----
        fft8p(a, M1, RH2, NRH2);

        // ---- window + overlap-add epilogue ----
        const bool sA = (fA >= fstart);
        const bool sB = (fB <= fstart + 7);
        #pragma unroll
        for (int j = 0; j < 4; ++j) {
            int n1 = t + 64 * j;
            float reA, reB, imA, imB, r2A, r2B, i2A, i2B;
            UNPK(a[j].re, reA, reB);     UNPK(a[j].im, imA, imB);
            UNPK(a[j + 4].re, r2A, r2B); UNPK(a[j + 4].im, i2A, i2B);
            float2 w1 = wA[j];
            float2 w2 = wA[j + 4];
            if (sA) {
                float2 o;
                o.x = reA * w1.x + carry[j].x;
                o.y = imA * w1.y + carry[j].y;
                *(float2*)(outp + (size_t)fA * STEP + 2 * n1) = o;
            }
            if (sB) {
                float2 o;
                o.x = reB * w1.x + r2A * w2.x;
                o.y = imB * w1.y + i2A * w2.y;
                *(float2*)(outp + (size_t)fB * STEP + 2 * n1) = o;
            }
            carry[j] = make_float2(r2B * w2.x, i2B * w2.y);
        }

        // ---- advance decay by d^2 (both lanes; sign pattern preserved) ----
        #pragma unroll
        for (int r = 0; r < 8; ++r) {
            int k = t + 64 * r;
            wk2[r] = PMUL(wk2[r], PDUP(sd2[k]));
            wq2[r] = PMUL(wq2[r], PDUP(sd2[512 - k]));
        }
    }
}

// ---------------------------------------------------------------------------
extern "C" void kernel_launch(void* const* d_in, const int* in_sizes, int n_in,
                              void* d_out, int out_size) {
    const float* amp   = (const float*)d_in[0];
    const float* phase = (const float*)d_in[1];
    const float* decay = (const float*)d_in[2];
    float* out = (float*)d_out;

    int total = 64 * NCO * 4;
    init_base_kernel<<<(total + 255) / 256, 256>>>(amp, phase, decay);
    init_pack_kernel<<<(NPAIRS * 512 + 255) / 256, 256>>>();

    dim3 grid(NPAIRS, 4);
    synth_kernel<<<grid, 256>>>(out);
}